// round 1
// baseline (speedup 1.0000x reference)
#include <cuda_runtime.h>
#include <math.h>

#define N_TOTAL 4096
#define T_ 32
#define D_ 158
#define NEWS_ 1024
#define DGRU_ 128
#define HID_ 64
#define AGGW 1184  // 1024 news + 158 price + 2 pad (so K-loop is exact multiple of 16)

// out layout (float32, tuple flatten+concat):
// pred    [0, 4096)
// rw1     [4096, 266240)
// hidden  [266240, 528384)
// topk    [528384, 536576)   (indices cast to float)
// rw2     [536576, 798720)
#define OFF_PRED 0
#define OFF_RW1 4096
#define OFF_HID 266240
#define OFF_TOPK 528384
#define OFF_RW2 536576

__device__ float g_agg[N_TOTAL * AGGW];

// ---------------------------------------------------------------------------
// Kernel A: masked news mean + price mean -> g_agg  (HBM streaming, 592 MB)
// agg row layout: [0..1023] news_agg, [1024..1181] price_agg, [1182..1183] 0
// ---------------------------------------------------------------------------
__global__ void kernelA(const float* __restrict__ price,
                        const float* __restrict__ news,
                        const float* __restrict__ mask) {
    int n = blockIdx.x;
    int tid = threadIdx.x;
    __shared__ float sm[T_];
    __shared__ float sinv;
    if (tid < T_) sm[tid] = mask[n * T_ + tid];
    __syncthreads();
    if (tid == 0) {
        float s = 0.f;
        #pragma unroll
        for (int t = 0; t < T_; t++) s += sm[t];
        sinv = 1.0f / fmaxf(s, 1e-6f);
    }
    __syncthreads();

    // news: 1024 floats = 256 float4 columns, one per thread
    const float4* news4 = (const float4*)(news + (size_t)n * T_ * NEWS_);
    float4 acc = make_float4(0.f, 0.f, 0.f, 0.f);
    #pragma unroll 4
    for (int t = 0; t < T_; t++) {
        float mt = sm[t];
        float4 v = news4[t * 256 + tid];
        acc.x += mt * v.x; acc.y += mt * v.y;
        acc.z += mt * v.z; acc.w += mt * v.w;
    }
    float inv = sinv;
    acc.x *= inv; acc.y *= inv; acc.z *= inv; acc.w *= inv;
    ((float4*)(g_agg + (size_t)n * AGGW))[tid] = acc;

    // price: 158 floats
    if (tid < D_) {
        const float* p = price + (size_t)n * T_ * D_ + tid;
        float a = 0.f;
        #pragma unroll 4
        for (int t = 0; t < T_; t++) a += p[t * D_];
        g_agg[(size_t)n * AGGW + NEWS_ + tid] = a * (1.0f / 32.0f);
    } else if (tid < 160) {
        g_agg[(size_t)n * AGGW + NEWS_ + tid] = 0.0f;  // pad cols 1182,1183
    }
}

// ---------------------------------------------------------------------------
// Kernel B: h = tanh(agg @ router_W + router_b); hidden = h @ gate_W + gate_b
// Tile: 32 rows x 128 cols, K chunks of 16. 256 threads, 4x4 microtiles.
// hidden written directly into d_out hidden region.
// ---------------------------------------------------------------------------
__global__ void kernelB(const float* __restrict__ router_W,
                        const float* __restrict__ router_b,
                        const float* __restrict__ gate_W,
                        const float* __restrict__ gate_b,
                        float* __restrict__ out_hidden) {
    __shared__ union {
        struct { float A[32][16]; float B[16][128]; } g;
        float h[32][128];
    } u;                                  // 16 KB
    __shared__ float sGate[128][64];      // 32 KB

    int tid = threadIdx.x;
    int n0 = blockIdx.x * 32;

    for (int i = tid; i < 128 * 64; i += 256) sGate[i >> 6][i & 63] = gate_W[i];

    int tr = tid >> 5;   // 0..7  -> rows tr*4 .. tr*4+3
    int tc = tid & 31;   // 0..31 -> cols tc*4 .. tc*4+3
    float acc[4][4] = {};

    for (int k0 = 0; k0 < AGGW; k0 += 16) {
        // load A tile 32x16
        #pragma unroll
        for (int i = 0; i < 2; i++) {
            int idx = tid + i * 256;
            int r = idx >> 4, c = idx & 15;
            u.g.A[r][c] = g_agg[(size_t)(n0 + r) * AGGW + k0 + c];
        }
        // load B tile 16x128 with row permutation (news first in agg)
        #pragma unroll
        for (int i = 0; i < 8; i++) {
            int idx = tid + i * 256;
            int kk = idx >> 7, j = idx & 127;
            int krow = k0 + kk;
            int wrow = (krow < 1024) ? (158 + krow) : min(krow - 1024, 157);
            u.g.B[kk][j] = router_W[wrow * 128 + j];
        }
        __syncthreads();
        #pragma unroll
        for (int k = 0; k < 16; k++) {
            float a0 = u.g.A[tr * 4 + 0][k];
            float a1 = u.g.A[tr * 4 + 1][k];
            float a2 = u.g.A[tr * 4 + 2][k];
            float a3 = u.g.A[tr * 4 + 3][k];
            float4 b = *(const float4*)&u.g.B[k][tc * 4];
            acc[0][0] += a0 * b.x; acc[0][1] += a0 * b.y; acc[0][2] += a0 * b.z; acc[0][3] += a0 * b.w;
            acc[1][0] += a1 * b.x; acc[1][1] += a1 * b.y; acc[1][2] += a1 * b.z; acc[1][3] += a1 * b.w;
            acc[2][0] += a2 * b.x; acc[2][1] += a2 * b.y; acc[2][2] += a2 * b.z; acc[2][3] += a2 * b.w;
            acc[3][0] += a3 * b.x; acc[3][1] += a3 * b.y; acc[3][2] += a3 * b.z; acc[3][3] += a3 * b.w;
        }
        __syncthreads();
    }

    // tanh + stash h tile in shared (overlaps GEMM tiles; acc is in registers)
    #pragma unroll
    for (int i = 0; i < 4; i++) {
        int r = tr * 4 + i;
        #pragma unroll
        for (int jj = 0; jj < 4; jj++) {
            int j = tc * 4 + jj;
            u.h[r][j] = tanhf(acc[i][jj] + router_b[j]);
        }
    }
    __syncthreads();

    // hidden = h @ gate_W + gate_b : 32x64 outputs, 8 per thread
    int r = tid >> 3;
    int c0 = (tid & 7) * 8;
    float hacc[8] = {};
    #pragma unroll 4
    for (int kk = 0; kk < 128; kk++) {
        float hv = u.h[r][kk];
        #pragma unroll
        for (int c = 0; c < 8; c++) hacc[c] += hv * sGate[kk][c0 + c];
    }
    #pragma unroll
    for (int c = 0; c < 8; c++)
        out_hidden[(size_t)(n0 + r) * HID_ + c0 + c] = hacc[c] + gate_b[c0 + c];
}

// ---------------------------------------------------------------------------
// Kernel C: per-row top-2 + masked softmax + expert/QKV/attention/output.
// 256 threads = 4 groups of 64; each group owns one row n; 8 iterations.
// ---------------------------------------------------------------------------
__global__ void kernelC(const float* __restrict__ expert_W,
                        const float* __restrict__ expert_b,
                        const float* __restrict__ wq, const float* __restrict__ wq_b,
                        const float* __restrict__ wk, const float* __restrict__ wk_b,
                        const float* __restrict__ wv, const float* __restrict__ wv_b,
                        const float* __restrict__ wo, const float* __restrict__ wo_b,
                        const float* __restrict__ hid_in,
                        float* __restrict__ out) {
    __shared__ float sWexp[64][64];                       // [h][g*8+e]
    __shared__ float sWq[8][64], sWk[8][64], sWv[8][64], sWo[8][64];  // [e][g*8+f]
    __shared__ float sEb[64], sQb[64], sKb[64], sVb[64], sOb[64];
    __shared__ float s_hid[4][64], s_eo[4][64];
    __shared__ float s_q[4][64], s_k[4][64], s_v[4][64], s_att[4][64];
    __shared__ int s_i1[4], s_i2[4];
    __shared__ float s_v1[4], s_den[4];

    int tid = threadIdx.x;
    for (int idx = tid; idx < 4096; idx += 256) {
        int ge = idx >> 6, h = idx & 63;
        sWexp[h][ge] = expert_W[idx];       // expert_W[(g*8+e)*64 + h]
    }
    for (int idx = tid; idx < 512; idx += 256) {
        int g = idx >> 6, f = (idx >> 3) & 7, e = idx & 7;
        int dst = e * 64 + g * 8 + f;
        ((float*)sWq)[dst] = wq[idx];
        ((float*)sWk)[dst] = wk[idx];
        ((float*)sWv)[dst] = wv[idx];
        ((float*)sWo)[dst] = wo[idx];
    }
    if (tid < 64) {
        sEb[tid] = expert_b[tid];
        sQb[tid] = wq_b[tid]; sKb[tid] = wk_b[tid];
        sVb[tid] = wv_b[tid]; sOb[tid] = wo_b[tid];
    }
    __syncthreads();

    int grp = tid >> 6;
    int j = tid & 63;
    int g = j >> 3;
    int base = g * 8;
    int hh = (j & 7) >> 1, d = j & 1;

    float* out_pred = out + OFF_PRED;
    float* out_rw1 = out + OFF_RW1;
    float* out_topk = out + OFF_TOPK;
    float* out_rw2 = out + OFF_RW2;

    for (int it = 0; it < 8; it++) {
        int n = blockIdx.x * 32 + it * 4 + grp;
        float hj = hid_in[(size_t)n * 64 + j];
        s_hid[grp][j] = hj;
        __syncthreads();

        if (j == 0) {
            float v1 = -1e38f; int i1 = 0;
            #pragma unroll 8
            for (int a = 0; a < 64; a++) {
                float v = s_hid[grp][a];
                if (v > v1) { v1 = v; i1 = a; }  // strict >: first occurrence wins (jax tie rule)
            }
            float v2 = -1e38f; int i2 = 0;
            #pragma unroll 8
            for (int a = 0; a < 64; a++) {
                if (a == i1) continue;
                float v = s_hid[grp][a];
                if (v > v2) { v2 = v; i2 = a; }
            }
            s_i1[grp] = i1; s_i2[grp] = i2; s_v1[grp] = v1;
            s_den[grp] = 1.0f + expf(v2 - v1);
        }
        __syncthreads();
        int i1 = s_i1[grp], i2 = s_i2[grp];
        float rw = 0.0f;
        if (j == i1) rw = 1.0f / s_den[grp];
        else if (j == i2) rw = expf(hj - s_v1[grp]) / s_den[grp];

        // expert_out[g*8+e] = b + sum_h hidden[h] * expert_W[g,e,h]
        float eo = sEb[j];
        #pragma unroll 8
        for (int h = 0; h < 64; h++) eo += s_hid[grp][h] * sWexp[h][j];
        s_eo[grp][j] = eo;
        __syncthreads();

        // q/k/v[g*8+f] = b + sum_e eo[g*8+e] * w[g,f,e]
        float qv = sQb[j], kv = sKb[j], vv = sVb[j];
        #pragma unroll
        for (int e = 0; e < 8; e++) {
            float x = s_eo[grp][base + e];
            qv += x * sWq[e][j];
            kv += x * sWk[e][j];
            vv += x * sWv[e][j];
        }
        s_q[grp][j] = qv; s_k[grp][j] = kv; s_v[grp][j] = vv;
        __syncthreads();

        // attention: j = g*8 + (hh*2 + d).
        // scores[g,d,e'] = (1/sqrt(2)) sum_a q[g,2a+d]*k[g,2a+e'], softmax over e' in {0,1}
        float s0 = 0.f, s1 = 0.f;
        #pragma unroll
        for (int a = 0; a < 4; a++) {
            float qa = s_q[grp][base + 2 * a + d];
            s0 += qa * s_k[grp][base + 2 * a];
            s1 += qa * s_k[grp][base + 2 * a + 1];
        }
        const float sc = 0.70710678118654752440f;
        s0 *= sc; s1 *= sc;
        float mx = fmaxf(s0, s1);
        float e0 = expf(s0 - mx), e1 = expf(s1 - mx);
        float rs = 1.0f / (e0 + e1);
        float att = (e0 * rs) * s_v[grp][base + 2 * hh]
                  + (e1 * rs) * s_v[grp][base + 2 * hh + 1];
        s_att[grp][j] = att;
        __syncthreads();

        // agg[g*8+f] = b + sum_e att[g*8+e] * wo[g,f,e]
        float ag = sOb[j];
        #pragma unroll
        for (int e = 0; e < 8; e++) ag += s_att[grp][base + e] * sWo[e][j];

        out_rw1[(size_t)n * 64 + j] = rw;
        out_rw2[(size_t)n * 64 + j] = rw;

        s_hid[grp][j] = ag * rw;   // reuse as weighted buffer
        __syncthreads();
        if (j == 0) {
            out_pred[n] = s_hid[grp][i1] + s_hid[grp][i2];  // only nonzero terms
            out_topk[n * 2 + 0] = (float)i1;
            out_topk[n * 2 + 1] = (float)i2;
        }
        __syncthreads();   // protect shared buffers before next iteration
    }
}

// ---------------------------------------------------------------------------
extern "C" void kernel_launch(void* const* d_in, const int* in_sizes, int n_in,
                              void* d_out, int out_size) {
    const float* price    = (const float*)d_in[0];
    const float* news     = (const float*)d_in[1];
    const float* mask     = (const float*)d_in[2];
    const float* router_W = (const float*)d_in[3];
    const float* router_b = (const float*)d_in[4];
    const float* gate_W   = (const float*)d_in[5];
    const float* gate_b   = (const float*)d_in[6];
    const float* expert_W = (const float*)d_in[7];
    const float* expert_b = (const float*)d_in[8];
    const float* wq   = (const float*)d_in[9];
    const float* wq_b = (const float*)d_in[10];
    const float* wk   = (const float*)d_in[11];
    const float* wk_b = (const float*)d_in[12];
    const float* wv   = (const float*)d_in[13];
    const float* wv_b = (const float*)d_in[14];
    const float* wo   = (const float*)d_in[15];
    const float* wo_b = (const float*)d_in[16];
    float* out = (float*)d_out;

    kernelA<<<N_TOTAL, 256>>>(price, news, mask);
    kernelB<<<128, 256>>>(router_W, router_b, gate_W, gate_b, out + OFF_HID);
    kernelC<<<128, 256>>>(expert_W, expert_b, wq, wq_b, wk, wk_b, wv, wv_b,
                          wo, wo_b, out + OFF_HID, out);
}

// round 2
// speedup vs baseline: 1.1268x; 1.1268x over previous
#include <cuda_runtime.h>
#include <math.h>

#define N_TOTAL 4096
#define T_ 32
#define D_ 158
#define NEWS_ 1024
#define AGGW 1184          // 1024 news + 158 price + 2 pad (74 * 16)
#define ROWS_PB 16
#define NBLK (N_TOTAL / ROWS_PB)   // 256

// out layout (float32): pred | rw | hidden | topk | rw
#define OFF_PRED 0
#define OFF_RW1 4096
#define OFF_HID 266240
#define OFF_TOPK 528384
#define OFF_RW2 536576

__device__ float g_agg[N_TOTAL * AGGW];

struct Smem {
    union {
        struct {
            float A[2][16][16];     // 2 KB
            float B[2][16][128];    // 16 KB
        } db;
        float h[16][128];           // 8 KB (reused after GEMM)
    } u;
    float gate[128][64];            // 32 KB
    float wexp[64][64];             // 16 KB  [h][g*8+e]
    float wq[8][64], wk[8][64], wv[8][64], wo[8][64];  // 8 KB  [e][g*8+f]
    float eb[64], qb[64], kb[64], vb[64], ob[64];
    float rb[128];
    float gb[64];
    float mask[16][32];
    float minv[16];
    float h16[16][64];
    float eo[4][64], q[4][64], v[4][64], att[4][64], kk_[4][64], wbuf[4][64];
    int   i1[4], i2[4];
    float v1[4], den[4];
};

extern __shared__ unsigned char smem_raw[];

__global__ void __launch_bounds__(256, 2)
fused_kernel(const float* __restrict__ price,
             const float* __restrict__ news,
             const float* __restrict__ maskp,
             const float* __restrict__ router_W,
             const float* __restrict__ router_b,
             const float* __restrict__ gate_W,
             const float* __restrict__ gate_b,
             const float* __restrict__ expert_W,
             const float* __restrict__ expert_b,
             const float* __restrict__ wq, const float* __restrict__ wq_b,
             const float* __restrict__ wk, const float* __restrict__ wk_b,
             const float* __restrict__ wv, const float* __restrict__ wv_b,
             const float* __restrict__ wo, const float* __restrict__ wo_b,
             float* __restrict__ out) {
    Smem& s = *reinterpret_cast<Smem*>(smem_raw);
    const int tid = threadIdx.x;
    const int n0 = blockIdx.x * ROWS_PB;

    // ---------------- stage weights + mask into shared ----------------
    for (int idx = tid; idx < 128 * 64; idx += 256)
        s.gate[idx >> 6][idx & 63] = gate_W[idx];
    for (int idx = tid; idx < 4096; idx += 256) {
        int ge = idx >> 6, h = idx & 63;
        s.wexp[h][ge] = expert_W[idx];
    }
    for (int idx = tid; idx < 512; idx += 256) {
        int g = idx >> 6, f = (idx >> 3) & 7, e = idx & 7;
        int dst = e * 64 + g * 8 + f;
        ((float*)s.wq)[dst] = wq[idx];
        ((float*)s.wk)[dst] = wk[idx];
        ((float*)s.wv)[dst] = wv[idx];
        ((float*)s.wo)[dst] = wo[idx];
    }
    if (tid < 64) {
        s.eb[tid] = expert_b[tid];
        s.qb[tid] = wq_b[tid]; s.kb[tid] = wk_b[tid];
        s.vb[tid] = wv_b[tid]; s.ob[tid] = wo_b[tid];
        s.gb[tid] = gate_b[tid];
    }
    if (tid < 128) s.rb[tid] = router_b[tid];
    for (int idx = tid; idx < ROWS_PB * T_; idx += 256)
        s.mask[idx >> 5][idx & 31] = maskp[(size_t)n0 * T_ + idx];
    __syncthreads();
    if (tid < ROWS_PB) {
        float ssum = 0.f;
        #pragma unroll
        for (int t = 0; t < T_; t++) ssum += s.mask[tid][t];
        s.minv[tid] = 1.0f / fmaxf(ssum, 1e-6f);
    }
    __syncthreads();

    // ---------------- phase 1: streaming aggregation ----------------
    {
        const float4* nb = (const float4*)news;
        for (int r = 0; r < ROWS_PB; r++) {
            const float4* p = nb + (size_t)(n0 + r) * T_ * 256 + tid;
            float4 acc = make_float4(0.f, 0.f, 0.f, 0.f);
            #pragma unroll 8
            for (int t = 0; t < T_; t++) {
                float mt = s.mask[r][t];
                float4 v = p[(size_t)t * 256];
                acc.x += mt * v.x; acc.y += mt * v.y;
                acc.z += mt * v.z; acc.w += mt * v.w;
            }
            float inv = s.minv[r];
            acc.x *= inv; acc.y *= inv; acc.z *= inv; acc.w *= inv;
            ((float4*)(g_agg + (size_t)(n0 + r) * AGGW))[tid] = acc;
        }
    }
    if (tid < 160) {
        for (int r = 0; r < ROWS_PB; r++) {
            float a = 0.f;
            if (tid < D_) {
                const float* p = price + (size_t)(n0 + r) * T_ * D_ + tid;
                #pragma unroll 8
                for (int t = 0; t < T_; t++) a += p[t * D_];
                a *= (1.0f / 32.0f);
            }
            g_agg[(size_t)(n0 + r) * AGGW + NEWS_ + tid] = a;  // pads write 0
        }
    }
    __syncthreads();

    // ---------------- phase 2: router GEMM (16x1184x128) ----------------
    // warps 0-3: consumers (4x4 microtile). warps 4-7: producers (double-buffer).
    float acc[4][4] = {};
    const int tr = tid >> 5;       // consumer: 0..3
    const int tc = tid & 31;
    const int pth = tid - 128;     // producer: 0..127

    if (tid >= 128) {
        // load tile 0
        #pragma unroll
        for (int i = 0; i < 2; i++) {
            int idx = pth + i * 128;
            int r = idx >> 4, c = idx & 15;
            s.u.db.A[0][r][c] = g_agg[(size_t)(n0 + r) * AGGW + c];
        }
        #pragma unroll
        for (int i = 0; i < 16; i++) {
            int krow = i;
            int wrow = 158 + krow;   // k0=0 < 1024 always news region
            s.u.db.B[0][i][pth] = router_W[wrow * 128 + pth];
        }
    }
    __syncthreads();

    for (int t = 0; t < 74; t++) {
        int cur = t & 1;
        if (tid >= 128 && t < 73) {
            int nxt = cur ^ 1;
            int k0 = (t + 1) * 16;
            #pragma unroll
            for (int i = 0; i < 2; i++) {
                int idx = pth + i * 128;
                int r = idx >> 4, c = idx & 15;
                s.u.db.A[nxt][r][c] = g_agg[(size_t)(n0 + r) * AGGW + k0 + c];
            }
            #pragma unroll
            for (int i = 0; i < 16; i++) {
                int krow = k0 + i;
                int wrow = (krow < 1024) ? (158 + krow) : min(krow - 1024, 157);
                s.u.db.B[nxt][i][pth] = router_W[wrow * 128 + pth];
            }
        }
        if (tid < 128) {
            #pragma unroll
            for (int k = 0; k < 16; k++) {
                float a0 = s.u.db.A[cur][tr * 4 + 0][k];
                float a1 = s.u.db.A[cur][tr * 4 + 1][k];
                float a2 = s.u.db.A[cur][tr * 4 + 2][k];
                float a3 = s.u.db.A[cur][tr * 4 + 3][k];
                float4 b = *(const float4*)&s.u.db.B[cur][k][tc * 4];
                acc[0][0] += a0 * b.x; acc[0][1] += a0 * b.y; acc[0][2] += a0 * b.z; acc[0][3] += a0 * b.w;
                acc[1][0] += a1 * b.x; acc[1][1] += a1 * b.y; acc[1][2] += a1 * b.z; acc[1][3] += a1 * b.w;
                acc[2][0] += a2 * b.x; acc[2][1] += a2 * b.y; acc[2][2] += a2 * b.z; acc[2][3] += a2 * b.w;
                acc[3][0] += a3 * b.x; acc[3][1] += a3 * b.y; acc[3][2] += a3 * b.z; acc[3][3] += a3 * b.w;
            }
        }
        __syncthreads();
    }

    // tanh + write h into the union region (GEMM buffers dead now)
    if (tid < 128) {
        #pragma unroll
        for (int i = 0; i < 4; i++) {
            #pragma unroll
            for (int jj = 0; jj < 4; jj++) {
                int j = tc * 4 + jj;
                s.u.h[tr * 4 + i][j] = tanhf(acc[i][jj] + s.rb[j]);
            }
        }
    }
    __syncthreads();

    // ---------------- gate GEMM: hidden = h @ gate_W + gate_b ----------------
    {
        int r = tid >> 4;
        int c0 = (tid & 15) * 4;
        float hacc[4] = {};
        #pragma unroll 4
        for (int kk = 0; kk < 128; kk++) {
            float hv = s.u.h[r][kk];
            float4 gw = *(const float4*)&s.gate[kk][c0];
            hacc[0] += hv * gw.x; hacc[1] += hv * gw.y;
            hacc[2] += hv * gw.z; hacc[3] += hv * gw.w;
        }
        float* out_hid = out + OFF_HID;
        #pragma unroll
        for (int c = 0; c < 4; c++) {
            float val = hacc[c] + s.gb[c0 + c];
            out_hid[(size_t)(n0 + r) * 64 + c0 + c] = val;
            s.h16[r][c0 + c] = val;
        }
    }
    __syncthreads();

    // ---------------- phase 3: topk/softmax/experts/attention ----------------
    {
        const int grp = tid >> 6;
        const int j = tid & 63;
        const int g = j >> 3;
        const int base = g * 8;
        const int hh = (j & 7) >> 1, d = j & 1;

        float* out_pred = out + OFF_PRED;
        float* out_rw1 = out + OFF_RW1;
        float* out_topk = out + OFF_TOPK;
        float* out_rw2 = out + OFF_RW2;

        for (int it = 0; it < 4; it++) {
            int rl = it * 4 + grp;
            int n = n0 + rl;
            float hj = s.h16[rl][j];

            if (j == 0) {
                float v1 = -1e38f; int i1 = 0;
                #pragma unroll 8
                for (int a = 0; a < 64; a++) {
                    float v = s.h16[rl][a];
                    if (v > v1) { v1 = v; i1 = a; }
                }
                float v2 = -1e38f; int i2 = 0;
                #pragma unroll 8
                for (int a = 0; a < 64; a++) {
                    if (a == i1) continue;
                    float v = s.h16[rl][a];
                    if (v > v2) { v2 = v; i2 = a; }
                }
                s.i1[grp] = i1; s.i2[grp] = i2; s.v1[grp] = v1;
                s.den[grp] = 1.0f + expf(v2 - v1);
            }
            __syncthreads();
            int i1 = s.i1[grp], i2 = s.i2[grp];
            float rw = 0.0f;
            if (j == i1) rw = 1.0f / s.den[grp];
            else if (j == i2) rw = expf(hj - s.v1[grp]) / s.den[grp];

            // expert_out
            float eo = s.eb[j];
            #pragma unroll 8
            for (int h = 0; h < 64; h++) eo += s.h16[rl][h] * s.wexp[h][j];
            s.eo[grp][j] = eo;
            __syncthreads();

            // q, k, v
            float qv = s.qb[j], kv = s.kb[j], vv = s.vb[j];
            #pragma unroll
            for (int e = 0; e < 8; e++) {
                float x = s.eo[grp][base + e];
                qv += x * s.wq[e][j];
                kv += x * s.wk[e][j];
                vv += x * s.wv[e][j];
            }
            s.q[grp][j] = qv; s.kk_[grp][j] = kv; s.v[grp][j] = vv;
            __syncthreads();

            // 2x2 attention per (g, head)
            float s0 = 0.f, s1 = 0.f;
            #pragma unroll
            for (int a = 0; a < 4; a++) {
                float qa = s.q[grp][base + 2 * a + d];
                s0 += qa * s.kk_[grp][base + 2 * a];
                s1 += qa * s.kk_[grp][base + 2 * a + 1];
            }
            const float sc = 0.70710678118654752440f;
            s0 *= sc; s1 *= sc;
            float mx = fmaxf(s0, s1);
            float e0 = expf(s0 - mx), e1 = expf(s1 - mx);
            float rs = 1.0f / (e0 + e1);
            float att = (e0 * rs) * s.v[grp][base + 2 * hh]
                      + (e1 * rs) * s.v[grp][base + 2 * hh + 1];
            s.att[grp][j] = att;
            __syncthreads();

            // output projection + routing weight
            float ag = s.ob[j];
            #pragma unroll
            for (int e = 0; e < 8; e++) ag += s.att[grp][base + e] * s.wo[e][j];

            out_rw1[(size_t)n * 64 + j] = rw;
            out_rw2[(size_t)n * 64 + j] = rw;
            s.wbuf[grp][j] = ag * rw;
            __syncthreads();
            if (j == 0) {
                out_pred[n] = s.wbuf[grp][i1] + s.wbuf[grp][i2];
                out_topk[n * 2 + 0] = (float)i1;
                out_topk[n * 2 + 1] = (float)i2;
            }
            __syncthreads();
        }
    }
}

// ---------------------------------------------------------------------------
extern "C" void kernel_launch(void* const* d_in, const int* in_sizes, int n_in,
                              void* d_out, int out_size) {
    const float* price    = (const float*)d_in[0];
    const float* news     = (const float*)d_in[1];
    const float* mask     = (const float*)d_in[2];
    const float* router_W = (const float*)d_in[3];
    const float* router_b = (const float*)d_in[4];
    const float* gate_W   = (const float*)d_in[5];
    const float* gate_b   = (const float*)d_in[6];
    const float* expert_W = (const float*)d_in[7];
    const float* expert_b = (const float*)d_in[8];
    const float* wq   = (const float*)d_in[9];
    const float* wq_b = (const float*)d_in[10];
    const float* wk   = (const float*)d_in[11];
    const float* wk_b = (const float*)d_in[12];
    const float* wv   = (const float*)d_in[13];
    const float* wv_b = (const float*)d_in[14];
    const float* wo   = (const float*)d_in[15];
    const float* wo_b = (const float*)d_in[16];
    float* out = (float*)d_out;

    cudaFuncSetAttribute(fused_kernel,
                         cudaFuncAttributeMaxDynamicSharedMemorySize,
                         (int)sizeof(Smem));
    fused_kernel<<<NBLK, 256, sizeof(Smem)>>>(
        price, news, mask, router_W, router_b, gate_W, gate_b,
        expert_W, expert_b, wq, wq_b, wk, wk_b, wv, wv_b, wo, wo_b, out);
}